// round 7
// baseline (speedup 1.0000x reference)
#include <cuda_runtime.h>
#include <math.h>

#define Bb 32
#define Tt 64
#define Ss 256
#define Hh 512
#define Ee 256
#define Vv 32000
#define NHh 8
#define STEPS 63
#define NBLK2 296

// ---------------- scratch ----------------------------------------------------
#define O_KH   0
#define O_VH   (O_KH  + Bb*Ss*Hh)
#define O_H0   (O_VH  + Bb*Ss*Hh)
#define O_H1   (O_H0  + Bb*Hh)
#define O_H0P  (O_H1  + Bb*Hh)
#define O_Q    (O_H0P + Bb*Hh)
#define O_CTXR (O_Q   + Bb*Hh)
#define O_GH0  (O_CTXR+ 2*Bb*Hh)
#define O_GH1  (O_GH0 + Bb*3*Hh)
#define O_EG   (O_GH1 + Bb*3*Hh)
#define O_EMBA (O_EG  + STEPS*Bb*Ee)
#define O_COMB (O_EMBA+ STEPS*Bb*Hh)
#define O_O1   (O_COMB+ STEPS*Bb*2*Hh)
#define O_TOTAL (O_O1 + STEPS*Bb*Hh)

__device__ float g_buf[O_TOTAL];
__device__ unsigned g_cnt_arr[64];
__device__ unsigned g_gen_arr[64];

__device__ __forceinline__ float clip100(float v){ return fminf(fmaxf(v,-100.f),100.f); }
__device__ __forceinline__ float sigm(float x){ return 1.f/(1.f+expf(-x)); }

// ---------------- setup kernels ----------------------------------------------
__global__ void init_kernel(const float* __restrict__ dec, const float* __restrict__ bo,
                            float* h0, float* h1, float* ctxr0){
    int i = blockIdx.x*256 + threadIdx.x;
    if (i < Bb*Hh){
        float v = fminf(fmaxf(dec[i], -10.f), 10.f);
        h0[i] = v; h1[i] = v;
        ctxr0[i] = bo[i & 511];
    }
}

__global__ void reset_kernel(){
    if (threadIdx.x == 0 && blockIdx.x == 0){ g_cnt_arr[0] = 0u; g_gen_arr[0] = 0u; }
}

__global__ void zero_kernel(float* __restrict__ out){
    int i = blockIdx.x*256 + threadIdx.x;
    if (i < Bb*Vv){
        int b = i / Vv, v = i % Vv;
        out[(size_t)b*Tt*Vv + v] = 0.f;
    }
}

// gather embedding rows for all steps: Eg[t*32+b, :] = embt[tgt[b,t], :]
__global__ void gather_emb_kernel(const int* __restrict__ tgt,
                                  const float* __restrict__ embt, float* __restrict__ Eg){
    int idx = blockIdx.x*256 + threadIdx.x;       // 2016*256
    int row = idx >> 8, e = idx & 255;
    int t = row >> 5, b = row & 31;
    int tok = tgt[b*Tt + t];
    Eg[row*Ee + e] = embt[tok*Ee + e];
}

// ---------------- big tiled SGEMM, double-buffered ----------------------------
// mode: 0 plain, 1 clip100, 2 relu, 3 clip100 + scatter into [B,T,V] at t+1
__global__ void gemm128_kernel(const float* __restrict__ A, const float* __restrict__ W,
                               const float* __restrict__ bias, float* __restrict__ C,
                               int M, int N, int K, int mode){
    __shared__ float As[2][8][128];
    __shared__ float Ws[2][8][128];
    const int tid = threadIdx.x;
    const int bm = blockIdx.y * 128;
    const int bn = blockIdx.x * 128;
    const int lrow = tid >> 1;
    const int lk4  = (tid & 1) * 4;
    const int tx = tid & 15, ty = tid >> 4;

    float acc[8][8];
    #pragma unroll
    for (int i=0;i<8;i++)
        #pragma unroll
        for (int j=0;j<8;j++) acc[i][j]=0.f;

    float4 av, wv;
    auto ld = [&](int kb){
        av = make_float4(0.f,0.f,0.f,0.f);
        int ar = bm + lrow;
        if (ar < M) av = *(const float4*)(A + (size_t)ar*K + kb + lk4);
        wv = *(const float4*)(W + (size_t)(bn+lrow)*K + kb + lk4);
    };
    auto st = [&](int p){
        As[p][lk4+0][lrow]=av.x; As[p][lk4+1][lrow]=av.y;
        As[p][lk4+2][lrow]=av.z; As[p][lk4+3][lrow]=av.w;
        Ws[p][lk4+0][lrow]=wv.x; Ws[p][lk4+1][lrow]=wv.y;
        Ws[p][lk4+2][lrow]=wv.z; Ws[p][lk4+3][lrow]=wv.w;
    };

    ld(0); st(0);
    __syncthreads();
    int p = 0;
    for (int kb = 0; kb < K; kb += 8){
        if (kb + 8 < K) ld(kb + 8);          // prefetch next chunk (overlaps compute)
        #pragma unroll
        for (int k=0;k<8;k++){
            float4 a0 = *(const float4*)&As[p][k][ty*4];
            float4 a1 = *(const float4*)&As[p][k][64 + ty*4];
            float4 b0 = *(const float4*)&Ws[p][k][tx*4];
            float4 b1 = *(const float4*)&Ws[p][k][64 + tx*4];
            float am[8] = {a0.x,a0.y,a0.z,a0.w, a1.x,a1.y,a1.z,a1.w};
            float bm_[8]= {b0.x,b0.y,b0.z,b0.w, b1.x,b1.y,b1.z,b1.w};
            #pragma unroll
            for (int i=0;i<8;i++)
                #pragma unroll
                for (int j=0;j<8;j++)
                    acc[i][j] += am[i]*bm_[j];
        }
        if (kb + 8 < K) st(p ^ 1);
        __syncthreads();
        p ^= 1;
    }

    #pragma unroll
    for (int i=0;i<8;i++){
        int gm = bm + (i<4 ? ty*4+i : 64 + ty*4 + (i-4));
        if (gm >= M) continue;
        #pragma unroll
        for (int j=0;j<8;j++){
            int gn = bn + (j<4 ? tx*4+j : 64 + tx*4 + (j-4));
            float v = acc[i][j] + bias[gn];
            if (mode==1 || mode==3) v = clip100(v);
            else if (mode==2)       v = fmaxf(v, 0.f);
            if (mode==3){
                int b = gm & 31, t = gm >> 5;
                C[((size_t)b*Tt + t + 1)*Vv + gn] = v;
            } else {
                C[(size_t)gm*N + gn] = v;
            }
        }
    }
}

// ---------------- persistent decoder loop -------------------------------------
struct SmemG { float As[32*132]; float Ws[32*128]; };
struct SmemA { float qs4[4][64]; float sc[256]; float red[64];
               float psum[4][64]; float ctxv[4][64]; };
union SmemU { SmemG g; SmemA a; };

struct Params {
    const int* mask;
    const float* wq;   const float* bq;
    const float* wo;
    const float* bo;
    const float* w_ih0; const float* w_hh0; const float* b_ih0; const float* b_hh0;
    const float* w_ih1; const float* w_hh1; const float* b_ih1; const float* b_hh1;
    const float* Kh; const float* Vh; const float* emba;
    float *h0, *h1, *h0p, *q, *ctxr, *gh0, *gh1, *comb;
};

__device__ __forceinline__ void grid_bar(unsigned target){
    __syncthreads();
    if (threadIdx.x == 0){
        __threadfence();
        unsigned prev = atomicAdd(&g_cnt_arr[0], 1u);
        if (prev == target*NBLK2 - 1u){
            __threadfence();
            asm volatile("st.release.gpu.u32 [%0], %1;" :: "l"(&g_gen_arr[0]), "r"(target) : "memory");
        } else {
            unsigned v;
            do {
                asm volatile("ld.acquire.gpu.u32 %0, [%1];" : "=r"(v) : "l"(&g_gen_arr[0]) : "memory");
            } while (v < target);
        }
    }
    __syncthreads();
}

// block reductions over 256 threads (2 syncs each), scratch red[>=8]
__device__ __forceinline__ float block_max(float v, float* red){
    #pragma unroll
    for (int off=16; off>0; off>>=1) v = fmaxf(v, __shfl_xor_sync(0xffffffffu, v, off));
    if ((threadIdx.x & 31) == 0) red[threadIdx.x >> 5] = v;
    __syncthreads();
    if (threadIdx.x < 8){
        float x = red[threadIdx.x];
        #pragma unroll
        for (int off=4; off>0; off>>=1) x = fmaxf(x, __shfl_xor_sync(0xffu, x, off));
        if (threadIdx.x == 0) red[0] = x;
    }
    __syncthreads();
    float r = red[0];
    __syncthreads();
    return r;
}
__device__ __forceinline__ float block_sum(float v, float* red){
    #pragma unroll
    for (int off=16; off>0; off>>=1) v += __shfl_xor_sync(0xffffffffu, v, off);
    if ((threadIdx.x & 31) == 0) red[threadIdx.x >> 5] = v;
    __syncthreads();
    if (threadIdx.x < 8){
        float x = red[threadIdx.x];
        #pragma unroll
        for (int off=4; off>0; off>>=1) x += __shfl_xor_sync(0xffu, x, off);
        if (threadIdx.x == 0) red[0] = x;
    }
    __syncthreads();
    float r = red[0];
    __syncthreads();
    return r;
}

// M=32 GEMM with register prefetch. lane = batch row, warp covers NW cols.
template<int NW>
__device__ void gemm_task(SmemU* sm, int n0, const float* __restrict__ A,
                          int K, const float* __restrict__ W, const float* __restrict__ bias,
                          float* __restrict__ C, int ldc, int act)
{
    const int tid = threadIdx.x;
    const int lane = tid & 31;
    const int wp = tid >> 5;
    float acc[NW];
    #pragma unroll
    for (int i=0;i<NW;i++) acc[i]=0.f;

    float4 pa[4];
    float4 pw[NW];
    auto loadA = [&](int kb){
        #pragma unroll
        for (int p2=0;p2<4;p2++){
            int idx = tid + p2*256;
            int r = idx >> 5, c4 = (idx & 31)*4;
            pa[p2] = *(const float4*)(A + r*512 + kb + c4);
        }
    };
    auto loadW = [&](int kb){
        #pragma unroll
        for (int q2=0;q2<NW;q2++){
            int idx = tid + q2*256;
            int n = idx >> 5, c4 = (idx & 31)*4;
            pw[q2] = *(const float4*)(W + (size_t)(n0+n)*K + kb + c4);
        }
    };

    loadA(0); loadW(0);
    for (int kb=0; kb<K; kb+=128){
        __syncthreads();
        #pragma unroll
        for (int p2=0;p2<4;p2++){
            int idx = tid + p2*256;
            int r = idx >> 5, c4 = (idx & 31)*4;
            *(float4*)&sm->g.As[r*132 + c4] = pa[p2];
        }
        #pragma unroll
        for (int q2=0;q2<NW;q2++){
            int idx = tid + q2*256;
            int n = idx >> 5, c4 = (idx & 31)*4;
            *(float4*)&sm->g.Ws[n*128 + c4] = pw[q2];
        }
        __syncthreads();
        if (kb + 128 < K){ loadA(kb+128); loadW(kb+128); }
        #pragma unroll
        for (int kc=0; kc<128; kc+=32){
            float a[32];
            #pragma unroll
            for (int j=0;j<32;j+=4)
                *(float4*)&a[j] = *(const float4*)&sm->g.As[lane*132 + kc + j];
            #pragma unroll
            for (int nn=0;nn<NW;nn++){
                const float* wr = &sm->g.Ws[(wp*NW+nn)*128 + kc];
                float s0=0.f, s1=0.f;
                #pragma unroll
                for (int j=0;j<32;j+=8){
                    float4 w0 = *(const float4*)(wr + j);
                    float4 w1 = *(const float4*)(wr + j + 4);
                    s0 += a[j+0]*w0.x + a[j+1]*w0.y + a[j+2]*w0.z + a[j+3]*w0.w;
                    s1 += a[j+4]*w1.x + a[j+5]*w1.y + a[j+6]*w1.z + a[j+7]*w1.w;
                }
                acc[nn] += s0 + s1;
            }
        }
    }
    #pragma unroll
    for (int nn=0;nn<NW;nn++){
        int n = n0 + wp*NW + nn;
        float v = acc[nn] + bias[n];
        if (act) v = clip100(v);
        C[lane*ldc + n] = v;
    }
}

// fused GEMM-triplet + GRU nonlinearity. Warp wp computes gate rows
// {j, j+512, j+1024} with j = n0+wp, then applies the GRU cell for all 32 batches.
// KK=1024: A = [emba_t | clip100(ctx_raw)]; KK=512: A plain.
template<int KK>
__device__ void gru_task(SmemU* sm, int n0, const float* __restrict__ A,
                         const float* __restrict__ ctx,
                         const float* __restrict__ W, const float* __restrict__ b_ih,
                         const float* __restrict__ gh,
                         float* __restrict__ hstate, float* __restrict__ hpre,
                         float* __restrict__ comb, const float* __restrict__ ctxr)
{
    const int tid = threadIdx.x;
    const int lane = tid & 31;
    const int wp = tid >> 5;
    float acc0=0.f, acc1=0.f, acc2=0.f;

    float4 pa[4];
    float4 pw[3];
    auto loadA = [&](int kb){
        #pragma unroll
        for (int p2=0;p2<4;p2++){
            int idx = tid + p2*256;
            int r = idx >> 5, c4 = (idx & 31)*4;
            if (KK == 1024){
                int kk = kb + c4;
                if (kk < 512) pa[p2] = *(const float4*)(A + r*512 + kk);
                else {
                    float4 v = *(const float4*)(ctx + r*512 + kk - 512);
                    v.x=clip100(v.x); v.y=clip100(v.y); v.z=clip100(v.z); v.w=clip100(v.w);
                    pa[p2] = v;
                }
            } else {
                pa[p2] = *(const float4*)(A + r*512 + kb + c4);
            }
        }
    };
    auto loadW = [&](int kb){
        #pragma unroll
        for (int q2=0;q2<3;q2++){
            int idx = tid + q2*256;
            int nn = idx >> 5, c4 = (idx & 31)*4;   // nn in 0..23
            int w = nn / 3, g = nn % 3;
            int grow = n0 + w + g*512;
            pw[q2] = *(const float4*)(W + (size_t)grow*KK + kb + c4);
            // store position: smem row (w*3+g)
        }
    };

    loadA(0); loadW(0);
    for (int kb=0; kb<KK; kb+=128){
        __syncthreads();
        #pragma unroll
        for (int p2=0;p2<4;p2++){
            int idx = tid + p2*256;
            int r = idx >> 5, c4 = (idx & 31)*4;
            *(float4*)&sm->g.As[r*132 + c4] = pa[p2];
        }
        #pragma unroll
        for (int q2=0;q2<3;q2++){
            int idx = tid + q2*256;
            int nn = idx >> 5, c4 = (idx & 31)*4;
            int w = nn / 3, g = nn % 3;
            *(float4*)&sm->g.Ws[(w*3+g)*128 + c4] = pw[q2];
        }
        __syncthreads();
        if (kb + 128 < KK){ loadA(kb+128); loadW(kb+128); }
        #pragma unroll
        for (int kc=0; kc<128; kc+=32){
            float a[32];
            #pragma unroll
            for (int j=0;j<32;j+=4)
                *(float4*)&a[j] = *(const float4*)&sm->g.As[lane*132 + kc + j];
            #pragma unroll
            for (int g=0; g<3; g++){
                const float* wr = &sm->g.Ws[(wp*3+g)*128 + kc];
                float s0=0.f, s1=0.f;
                #pragma unroll
                for (int j=0;j<32;j+=8){
                    float4 w0 = *(const float4*)(wr + j);
                    float4 w1 = *(const float4*)(wr + j + 4);
                    s0 += a[j+0]*w0.x + a[j+1]*w0.y + a[j+2]*w0.z + a[j+3]*w0.w;
                    s1 += a[j+4]*w1.x + a[j+5]*w1.y + a[j+6]*w1.z + a[j+7]*w1.w;
                }
                float s = s0 + s1;
                if (g==0) acc0 += s; else if (g==1) acc1 += s; else acc2 += s;
            }
        }
    }
    // GRU cell for (b=lane, j=n0+wp)
    const int j = n0 + wp, b = lane;
    float ir = acc0 + b_ih[j];
    float iz = acc1 + b_ih[j+512];
    float in_ = acc2 + b_ih[j+1024];
    const int gg = b*1536 + j;
    float r = sigm(ir + gh[gg]);
    float z = sigm(iz + gh[gg+512]);
    float n = tanhf(in_ + r*gh[gg+1024]);
    float hv = (1.f - z)*n + z*hstate[b*512 + j];
    if (hpre) hpre[b*512 + j] = hv;
    hstate[b*512 + j] = fminf(fmaxf(hv, -10.f), 10.f);
    if (comb){
        comb[b*1024 + j]       = hv;                      // pre-clip h1
        comb[b*1024 + 512 + j] = clip100(ctxr[b*512 + j]);
    }
}

// attention core for (head h, batch group bg of 4): scores/softmax/V + wo partials
__device__ void attn_core(SmemU* smu, const Params& P, int h, int bg, float* ctxr){
    SmemA* sa = &smu->a;
    const int tid = threadIdx.x;
    {   int bi = tid >> 6, d = tid & 63;
        sa->qs4[bi][d] = P.q[(bg*4+bi)*512 + h*64 + d]; }
    __syncthreads();

    for (int bi=0; bi<4; bi++){
        const int b = bg*4 + bi;
        const float* kp = P.Kh + ((size_t)(b*256 + tid))*512 + h*64;
        const float* qv = sa->qs4[bi];
        float s = 0.f;
        #pragma unroll
        for (int d=0; d<64; d+=4){
            float4 kv = *(const float4*)(kp + d);
            s += qv[d]*kv.x + qv[d+1]*kv.y + qv[d+2]*kv.z + qv[d+3]*kv.w;
        }
        s *= 0.125f;
        if (P.mask[b*256 + tid] == 0) s = -10000.f;
        float mx = block_max(s, sa->red);
        float e = expf(s - mx);
        sa->sc[tid] = e;
        float inv = 1.f / block_sum(e, sa->red);
        __syncthreads();
        {
            int d = tid & 63, part = tid >> 6;
            const float* vp = P.Vh + ((size_t)(b*256))*512 + h*64 + d;
            float p0=0.f, p1=0.f;
            #pragma unroll 4
            for (int s2 = part*64; s2 < part*64 + 64; s2 += 2){
                p0 += sa->sc[s2]   * vp[(size_t)s2*512];
                p1 += sa->sc[s2+1] * vp[(size_t)(s2+1)*512];
            }
            sa->psum[part][d] = p0 + p1;
        }
        __syncthreads();
        if (tid < 64)
            sa->ctxv[bi][tid] = (sa->psum[0][tid]+sa->psum[1][tid]
                               + sa->psum[2][tid]+sa->psum[3][tid]) * inv;
        __syncthreads();
    }
    // wo partials: ctx_raw[b, n] += sum_d ctxv[b][d] * wo[n, h*64+d]
    #pragma unroll
    for (int rr=0; rr<2; rr++){
        int n = tid + rr*256;
        const float4* wr = (const float4*)(P.wo + (size_t)n*512 + h*64);
        float s0=0.f, s1=0.f, s2=0.f, s3=0.f;
        #pragma unroll
        for (int j=0;j<16;j++){
            float4 w = wr[j];
            const float* c0 = &sa->ctxv[0][j*4];
            const float* c1 = &sa->ctxv[1][j*4];
            const float* c2 = &sa->ctxv[2][j*4];
            const float* c3 = &sa->ctxv[3][j*4];
            s0 += c0[0]*w.x + c0[1]*w.y + c0[2]*w.z + c0[3]*w.w;
            s1 += c1[0]*w.x + c1[1]*w.y + c1[2]*w.z + c1[3]*w.w;
            s2 += c2[0]*w.x + c2[1]*w.y + c2[2]*w.z + c2[3]*w.w;
            s3 += c3[0]*w.x + c3[1]*w.y + c3[2]*w.z + c3[3]*w.w;
        }
        atomicAdd(ctxr + (bg*4+0)*512 + n, s0);
        atomicAdd(ctxr + (bg*4+1)*512 + n, s1);
        atomicAdd(ctxr + (bg*4+2)*512 + n, s2);
        atomicAdd(ctxr + (bg*4+3)*512 + n, s3);
    }
}

#define PHASE(nt_, ...)                                               \
    for (int ti = (int)blockIdx.x; ti < (nt_); ti += NBLK2){          \
        __syncthreads();                                              \
        __VA_ARGS__                                                   \
    }                                                                 \
    bar++; grid_bar(bar);

__global__ void __launch_bounds__(256, 2) decoder_loop_kernel(Params P){
    __shared__ SmemU sm;
    const int tid = threadIdx.x;
    unsigned bar = 0;

    for (int t = 0; t < STEPS; t++){
        float* ctxc = P.ctxr + (t & 1)*Bb*Hh;

        // P1: qproj x64 + gh1 x64 + ctx-init x8  (136 tasks)
        PHASE(136, {
            if (ti < 64){
                gemm_task<1>(&sm, ti*8, P.h1, 512, P.wq, P.bq, P.q, 512, 1);
            } else if (ti < 128){
                gemm_task<3>(&sm, (ti-64)*24, P.h1, 512, P.w_hh1, P.b_hh1, P.gh1, 1536, 0);
            } else {
                int base = (ti-128)*2048 + tid;
                #pragma unroll
                for (int e=0;e<8;e++){
                    int idx = base + e*256;
                    ctxc[idx] = P.bo[idx & 511];
                }
            }
        })
        // P2: attn x64 + gh0 x64  (128 tasks)
        PHASE(128, {
            if (ti < 64){
                attn_core(&sm, P, ti >> 3, ti & 7, ctxc);
            } else {
                gemm_task<3>(&sm, (ti-64)*24, P.h0, 512, P.w_hh0, P.b_hh0, P.gh0, 1536, 0);
            }
        })
        // P3: gi0 + GRU0 fused  (64 tasks)
        PHASE(64, {
            gru_task<1024>(&sm, ti*8, P.emba + (size_t)t*Bb*Hh, ctxc,
                           P.w_ih0, P.b_ih0, P.gh0, P.h0, P.h0p, nullptr, nullptr);
        })
        // P4: gi1 + GRU1 fused + comb store  (64 tasks)
        PHASE(64, {
            gru_task<512>(&sm, ti*8, P.h0p, nullptr,
                          P.w_ih1, P.b_ih1, P.gh1, P.h1, nullptr,
                          P.comb + (size_t)t*Bb*2*Hh, ctxc);
        })
    }
}

// ---------------- driver -------------------------------------------------------
extern "C" void kernel_launch(void* const* d_in, const int* in_sizes, int n_in,
                              void* d_out, int out_size){
    const int*   tgt   = (const int*)  d_in[0];
    const float* enc   = (const float*)d_in[1];
    const float* dec   = (const float*)d_in[2];
    const int*   mask  = (const int*)  d_in[3];
    const float* embt  = (const float*)d_in[4];
    const float* w_ep  = (const float*)d_in[5];
    const float* b_ep  = (const float*)d_in[6];
    const float* wq    = (const float*)d_in[7];
    const float* bq    = (const float*)d_in[8];
    const float* wk    = (const float*)d_in[9];
    const float* bk    = (const float*)d_in[10];
    const float* wv    = (const float*)d_in[11];
    const float* bv    = (const float*)d_in[12];
    const float* wo    = (const float*)d_in[13];
    const float* bo    = (const float*)d_in[14];
    const float* w_ih0 = (const float*)d_in[15];
    const float* w_hh0 = (const float*)d_in[16];
    const float* b_ih0 = (const float*)d_in[17];
    const float* b_hh0 = (const float*)d_in[18];
    const float* w_ih1 = (const float*)d_in[19];
    const float* w_hh1 = (const float*)d_in[20];
    const float* b_ih1 = (const float*)d_in[21];
    const float* b_hh1 = (const float*)d_in[22];
    const float* w_o1  = (const float*)d_in[23];
    const float* b_o1  = (const float*)d_in[24];
    const float* w_o2  = (const float*)d_in[25];
    const float* b_o2  = (const float*)d_in[26];
    float* out = (float*)d_out;

    float* buf = nullptr;
    cudaGetSymbolAddress((void**)&buf, g_buf);

    Params P;
    P.mask = mask;
    P.wq = wq; P.bq = bq; P.wo = wo; P.bo = bo;
    P.w_ih0 = w_ih0; P.w_hh0 = w_hh0; P.b_ih0 = b_ih0; P.b_hh0 = b_hh0;
    P.w_ih1 = w_ih1; P.w_hh1 = w_hh1; P.b_ih1 = b_ih1; P.b_hh1 = b_hh1;
    P.Kh = buf + O_KH; P.Vh = buf + O_VH;
    P.h0 = buf + O_H0; P.h1 = buf + O_H1; P.h0p = buf + O_H0P;
    P.q = buf + O_Q; P.ctxr = buf + O_CTXR;
    P.gh0 = buf + O_GH0; P.gh1 = buf + O_GH1;
    P.emba = buf + O_EMBA;
    P.comb = buf + O_COMB;
    float* Eg = buf + O_EG;
    float* o1 = buf + O_O1;

    reset_kernel<<<1, 32>>>();
    init_kernel<<<(Bb*Hh+255)/256, 256>>>(dec, bo, P.h0, P.h1, P.ctxr);
    zero_kernel<<<(Bb*Vv+255)/256, 256>>>(out);

    // hoisted: embedding gather + projection for all 63 steps
    gather_emb_kernel<<<(STEPS*Bb*Ee)/256, 256>>>(tgt, embt, Eg);
    gemm128_kernel<<<dim3(Hh/128, (STEPS*Bb+127)/128), 256>>>(
        Eg, w_ep, b_ep, (float*)P.emba, STEPS*Bb, Hh, Ee, 0);

    // step-invariant K/V projections (Kh clipped, Vh plain)
    gemm128_kernel<<<dim3(Hh/128, (Bb*Ss)/128), 256>>>(enc, wk, bk, (float*)P.Kh, Bb*Ss, Hh, Hh, 1);
    gemm128_kernel<<<dim3(Hh/128, (Bb*Ss)/128), 256>>>(enc, wv, bv, (float*)P.Vh, Bb*Ss, Hh, Hh, 0);

    // full 63-step recurrence, 4 grid barriers per step
    decoder_loop_kernel<<<NBLK2, 256>>>(P);

    // batched output MLP over all 63 steps
    gemm128_kernel<<<dim3(Hh/128, (STEPS*Bb+127)/128), 256>>>(
        P.comb, w_o1, b_o1, o1, STEPS*Bb, Hh, 2*Hh, 2);           // relu
    gemm128_kernel<<<dim3(Vv/128, (STEPS*Bb+127)/128), 256>>>(
        o1, w_o2, b_o2, out, STEPS*Bb, Vv, Hh, 3);                // clip + scatter
}